// round 3
// baseline (speedup 1.0000x reference)
#include <cuda_runtime.h>
#include <cstdint>
#include <cstddef>

#define N_ 20000
#define E_ 640000
#define MB (1048576ull)

// ---------------- scratch layout (bytes, MiB units) ----------------
static const size_t O_SRC = 0;                 // int[2E]      4.88 MiB
static const size_t O_DST = 6*MB;              // int[2E]
static const size_t O_CSR = 12*MB;             // int[2E]
static const size_t O_CNT = 18*MB;             // int[2N]
static const size_t O_OFF = 19*MB;             // int[2N]
static const size_t O_CUR = 20*MB;             // int[2N]
static const size_t O_H1  = 21*MB;             // float[2*N*128]  19.53 MiB
static const size_t O_S1S = 41*MB;             // float[2*N*8]    1.22 MiB (2 MiB slot)
static const size_t O_S1D = 43*MB;             // float[2*N*8]
static const size_t O_H1C = 45*MB;             // float[N*128]    9.77 MiB
static const size_t O_S2S = 55*MB;             // float[2*N*8]
static const size_t O_S2D = 57*MB;             // float[2*N*8]
static const size_t O_WS  = 59*MB;             // float[16*128]
static const size_t O_WD  = 59*MB + 16384;
static const size_t O_W2C = 60*MB;             // float[2048*64]  0.5 MiB
static const size_t O_BC  = 60*MB + 524288;    // float[64]
static const size_t O_AGG = 61*MB;             // float[N*2048]   156.25 MiB
static const size_t O_H2P = 218*MB;            // float[N*64]     4.88 MiB
static const size_t SCRATCH_BYTES = 224*MB;

__device__ __align__(256) unsigned char g_scratch[SCRATCH_BYTES];
__device__ int g_mode;   // 1 = int64 indices, 0 = int32

__device__ __forceinline__ float eluf(float x) { return x > 0.f ? x : expm1f(x); }
__device__ __forceinline__ float lrelu(float x) { return x > 0.f ? x : 0.2f * x; }

// ---------------- index dtype detection ----------------
__global__ void k_detect(const unsigned int* p) {
    if (threadIdx.x == 0) {
        int is64 = 1;
        for (int i = 1; i < 64; i += 2)
            if (p[i] != 0u) is64 = 0;
        g_mode = is64;
    }
}

__global__ void k_zeroi(int* p, int n) {
    int i = blockIdx.x * blockDim.x + threadIdx.x;
    if (i < n) p[i] = 0;
}

// convert indices to int32 + histogram of dst
__global__ void k_cvt(const void* pa, const void* pb, int* src, int* dst, int* cnt) {
    int t = blockIdx.y;
    const void* p = t ? pb : pa;
    int i = blockIdx.x * blockDim.x + threadIdx.x;
    if (i >= E_) return;
    int s, d;
    if (g_mode) {
        const long long* q = (const long long*)p;
        s = (int)q[i]; d = (int)q[E_ + i];
    } else {
        const int* q = (const int*)p;
        s = q[i]; d = q[E_ + i];
    }
    src[t * E_ + i] = s;
    dst[t * E_ + i] = d;
    atomicAdd(&cnt[t * N_ + d], 1);
}

// exclusive scan of cnt per type (one block of 1024 per type)
__global__ void k_scan(const int* __restrict__ cnt, int* __restrict__ offs, int* __restrict__ cur)
{
    int t = blockIdx.x;
    const int* c = cnt + t * N_;
    int* o = offs + t * N_;
    int* q = cur + t * N_;
    __shared__ int wsum[32];
    __shared__ int sbase;
    int tid = threadIdx.x, lane = tid & 31, w = tid >> 5;
    if (tid == 0) sbase = 0;
    __syncthreads();
    for (int i0 = 0; i0 < N_; i0 += 1024) {
        int i = i0 + tid;
        int v = (i < N_) ? c[i] : 0;
        int x = v;
#pragma unroll
        for (int ofs = 1; ofs < 32; ofs <<= 1) {
            int y = __shfl_up_sync(0xffffffffu, x, ofs);
            if (lane >= ofs) x += y;
        }
        if (lane == 31) wsum[w] = x;
        __syncthreads();
        if (w == 0) {
            int s = wsum[lane];
#pragma unroll
            for (int ofs = 1; ofs < 32; ofs <<= 1) {
                int y = __shfl_up_sync(0xffffffffu, s, ofs);
                if (lane >= ofs) s += y;
            }
            wsum[lane] = s;
        }
        __syncthreads();
        int base = sbase + (w ? wsum[w - 1] : 0);
        int excl = base + x - v;
        if (i < N_) { o[i] = excl; q[i] = excl; }
        __syncthreads();
        if (tid == 0) sbase += wsum[31];
        __syncthreads();
    }
}

__global__ void k_scatter(const int* __restrict__ src, const int* __restrict__ dst,
                          int* __restrict__ cur, int* __restrict__ csr)
{
    int i = blockIdx.x * blockDim.x + threadIdx.x;
    if (i >= 2 * E_) return;
    int t = (i >= E_) ? 1 : 0;
    int e = i - t * E_;
    int s = src[t * E_ + e], d = dst[t * E_ + e];
    int pos = atomicAdd(&cur[t * N_ + d], 1);
    csr[(size_t)t * E_ + pos] = s;
}

// precompute: W2cat (scaled 1/16), score-projection vectors, combined bias
__global__ void k_prep(const float* __restrict__ W2, const float* __restrict__ a2s,
                       const float* __restrict__ a2d, const float* __restrict__ b2,
                       float* __restrict__ W2cat, float* __restrict__ ws,
                       float* __restrict__ wd, float* __restrict__ bc)
{
    int i = blockIdx.x * blockDim.x + threadIdx.x;
    if (i < 131072) {
        int o = i & 63, k = i >> 6;
        int t = k >> 10, r = k & 1023, h = r >> 7, c = r & 127;
        W2cat[i] = W2[t * 65536 + c * 512 + h * 64 + o] * 0.0625f;
    } else if (i < 133120) {
        int j = i - 131072;
        int t = j >> 10, r = j & 1023, h = r >> 7, c = r & 127;
        const float* wrow = W2 + t * 65536 + c * 512 + h * 64;
        const float* av = a2s + t * 512 + h * 64;
        float acc = 0.f;
        for (int o = 0; o < 64; o++) acc += wrow[o] * av[o];
        ws[j] = acc;
    } else if (i < 135168) {
        int j = i - 133120;
        int t = j >> 10, r = j & 1023, h = r >> 7, c = r & 127;
        const float* wrow = W2 + t * 65536 + c * 512 + h * 64;
        const float* av = a2d + t * 512 + h * 64;
        float acc = 0.f;
        for (int o = 0; o < 64; o++) acc += wrow[o] * av[o];
        wd[j] = acc;
    } else if (i < 135232) {
        int o = i - 135168;
        bc[o] = 0.5f * (b2[o] + b2[64 + o]);
    }
}

// ---------------- SGEMM (layer-1): C[b] = A @ B[b], 128x128 tile ----------------
template<int K>
__global__ void __launch_bounds__(256) k_sgemm(
    const float* __restrict__ A, const float* __restrict__ B,
    float* __restrict__ C, int n, int M)
{
    __shared__ float As[16][128];
    __shared__ float Bs[16][128];
    const int tid = threadIdx.x;
    const int rquad = (tid >> 4) << 2;
    const int cquad = (tid & 15) << 2;
    const int rowBase = blockIdx.x * 128;
    const int colBase = blockIdx.y * 128;
    const int b = blockIdx.z;
    const float* Bb = B + (size_t)b * K * M + colBase;
    float* Cb = C + (size_t)b * (size_t)n * M + colBase;

    float acc[8][8];
#pragma unroll
    for (int i = 0; i < 8; i++)
#pragma unroll
        for (int j = 0; j < 8; j++) acc[i][j] = 0.f;

    for (int k0 = 0; k0 < K; k0 += 16) {
#pragma unroll
        for (int i = 0; i < 2; i++) {
            int idx = tid + (i << 8);
            int r = idx >> 2;
            int c = (idx & 3) << 2;
            float4 v = make_float4(0.f, 0.f, 0.f, 0.f);
            int gr = rowBase + r;
            if (gr < n) v = *(const float4*)(A + (size_t)gr * K + k0 + c);
            As[c + 0][r] = v.x; As[c + 1][r] = v.y;
            As[c + 2][r] = v.z; As[c + 3][r] = v.w;
        }
#pragma unroll
        for (int i = 0; i < 2; i++) {
            int idx = tid + (i << 8);
            int r = idx >> 5;
            int c = (idx & 31) << 2;
            float4 v = *(const float4*)(Bb + (size_t)(k0 + r) * M + c);
            *(float4*)&Bs[r][c] = v;
        }
        __syncthreads();
#pragma unroll
        for (int kk = 0; kk < 16; kk++) {
            float a[8], bb[8];
            *(float4*)&a[0]  = *(const float4*)&As[kk][rquad];
            *(float4*)&a[4]  = *(const float4*)&As[kk][rquad + 64];
            *(float4*)&bb[0] = *(const float4*)&Bs[kk][cquad];
            *(float4*)&bb[4] = *(const float4*)&Bs[kk][cquad + 64];
#pragma unroll
            for (int i = 0; i < 8; i++)
#pragma unroll
                for (int j = 0; j < 8; j++)
                    acc[i][j] = fmaf(a[i], bb[j], acc[i][j]);
        }
        __syncthreads();
    }
#pragma unroll
    for (int i = 0; i < 8; i++) {
        int gr = rowBase + rquad + (i < 4 ? i : 64 + i - 4);
        if (gr < n) {
            *(float4*)(Cb + (size_t)gr * M + cquad) =
                make_float4(acc[i][0], acc[i][1], acc[i][2], acc[i][3]);
            *(float4*)(Cb + (size_t)gr * M + cquad + 64) =
                make_float4(acc[i][4], acc[i][5], acc[i][6], acc[i][7]);
        }
    }
}

// ---------------- layer-1 attention scores: warp per node ----------------
template<int C>
__global__ void k_scores(const float* __restrict__ h,
                         const float* __restrict__ a_src,
                         const float* __restrict__ a_dst,
                         float* __restrict__ ss, float* __restrict__ sd)
{
    const int ROW = 8 * C;
    int wid = (blockIdx.x * blockDim.x + threadIdx.x) >> 5;
    int lane = threadIdx.x & 31;
    int t = blockIdx.y;
    if (wid >= N_) return;
    const float* hr = h + (size_t)t * N_ * ROW + (size_t)wid * ROW;
    const float* as = a_src + t * ROW;
    const float* ad = a_dst + t * ROW;
    int head = lane >> 2;
    float ps = 0.f, pd = 0.f;
#pragma unroll
    for (int i = 0; i < C / 16; i++) {
        int off = lane * (ROW / 32) + i * 4;
        float4 v = *(const float4*)(hr + off);
        float4 w = *(const float4*)(as + off);
        float4 u = *(const float4*)(ad + off);
        ps += v.x * w.x + v.y * w.y + v.z * w.z + v.w * w.w;
        pd += v.x * u.x + v.y * u.y + v.z * u.z + v.w * u.w;
    }
    ps += __shfl_xor_sync(0xffffffffu, ps, 1);
    ps += __shfl_xor_sync(0xffffffffu, ps, 2);
    pd += __shfl_xor_sync(0xffffffffu, pd, 1);
    pd += __shfl_xor_sync(0xffffffffu, pd, 2);
    if ((lane & 3) == 0) {
        ss[t * N_ * 8 + wid * 8 + head] = ps;
        sd[t * N_ * 8 + wid * 8 + head] = pd;
    }
}

// ---------------- layer-1 GAT aggregate: warp per dst, CSR, no atomics ----------------
__global__ void __launch_bounds__(256) k_gat1(
    const int* __restrict__ offs, const int* __restrict__ cnt, const int* __restrict__ csr,
    const float* __restrict__ s1s, const float* __restrict__ s1d,
    const float* __restrict__ h1, const float* __restrict__ b1,
    float* __restrict__ h1c)
{
    int d = blockIdx.x * 8 + (threadIdx.x >> 5);
    int lane = threadIdx.x & 31;
    if (d >= N_) return;
    int h8 = lane & 7;
    int head = lane >> 2;
    float4 accsum = make_float4(0.f, 0.f, 0.f, 0.f);
    for (int t = 0; t < 2; t++) {
        const int* cs = csr + (size_t)t * E_;
        const float* ss = s1s + (size_t)t * N_ * 8;
        const float* sdp = s1d + (size_t)t * N_ * 8;
        const float* ht = h1 + (size_t)t * N_ * 128;
        int beg = offs[t * N_ + d], n = cnt[t * N_ + d];
        float sdv = __ldg(sdp + d * 8 + h8);
        float zp = 0.f;
        for (int e = 0; e < n; e += 4) {
            int idx = e + (lane >> 3);
            float val = 0.f;
            if (idx < n) {
                int s = cs[beg + idx];
                val = __expf(lrelu(__ldg(ss + s * 8 + h8) + sdv));
            }
            zp += val;
        }
        zp += __shfl_xor_sync(0xffffffffu, zp, 8);
        zp += __shfl_xor_sync(0xffffffffu, zp, 16);
        float inv = 1.f / zp;
        for (int e = 0; e < n; e += 4) {
            int idx = e + (lane >> 3);
            float val = 0.f; int smy = 0;
            if (idx < n) {
                smy = cs[beg + idx];
                val = __expf(lrelu(__ldg(ss + smy * 8 + h8) + sdv)) * inv;
            }
            int lim = n - e;
#pragma unroll
            for (int j = 0; j < 4; j++) {
                int sj = __shfl_sync(0xffffffffu, smy, j * 8);
                float aj = __shfl_sync(0xffffffffu, val, j * 8 + head);
                if (j < lim) {
                    float4 v = *(const float4*)(ht + (size_t)sj * 128 + lane * 4);
                    accsum.x = fmaf(aj, v.x, accsum.x);
                    accsum.y = fmaf(aj, v.y, accsum.y);
                    accsum.z = fmaf(aj, v.z, accsum.z);
                    accsum.w = fmaf(aj, v.w, accsum.w);
                }
            }
        }
    }
    float4 bb0 = *(const float4*)(b1 + lane * 4);
    float4 bb1 = *(const float4*)(b1 + 128 + lane * 4);
    float4 r;
    r.x = eluf(0.5f * (accsum.x + bb0.x + bb1.x));
    r.y = eluf(0.5f * (accsum.y + bb0.y + bb1.y));
    r.z = eluf(0.5f * (accsum.z + bb0.z + bb1.z));
    r.w = eluf(0.5f * (accsum.w + bb0.w + bb1.w));
    *(float4*)(h1c + (size_t)d * 128 + lane * 4) = r;
}

// ---------------- layer-2 scores from projected vectors: warp per node ----------------
__global__ void k_scores2(const float* __restrict__ h1c,
                          const float* __restrict__ ws, const float* __restrict__ wd,
                          float* __restrict__ s2s, float* __restrict__ s2d)
{
    int node = blockIdx.x * 8 + (threadIdx.x >> 5);
    int lane = threadIdx.x & 31;
    if (node >= N_) return;
    float4 v = *(const float4*)(h1c + (size_t)node * 128 + lane * 4);
#pragma unroll
    for (int c = 0; c < 16; c++) {
        float4 w = *(const float4*)(ws + c * 128 + lane * 4);
        float p = v.x * w.x + v.y * w.y + v.z * w.z + v.w * w.w;
        p += __shfl_xor_sync(0xffffffffu, p, 16);
        p += __shfl_xor_sync(0xffffffffu, p, 8);
        p += __shfl_xor_sync(0xffffffffu, p, 4);
        p += __shfl_xor_sync(0xffffffffu, p, 2);
        p += __shfl_xor_sync(0xffffffffu, p, 1);
        float4 u = *(const float4*)(wd + c * 128 + lane * 4);
        float q = v.x * u.x + v.y * u.y + v.z * u.z + v.w * u.w;
        q += __shfl_xor_sync(0xffffffffu, q, 16);
        q += __shfl_xor_sync(0xffffffffu, q, 8);
        q += __shfl_xor_sync(0xffffffffu, q, 4);
        q += __shfl_xor_sync(0xffffffffu, q, 2);
        q += __shfl_xor_sync(0xffffffffu, q, 1);
        if (lane == 0) {
            s2s[(c >> 3) * N_ * 8 + node * 8 + (c & 7)] = p;
            s2d[(c >> 3) * N_ * 8 + node * 8 + (c & 7)] = q;
        }
    }
}

// ---------------- layer-2 aggregate in h1c domain: warp per dst ----------------
__global__ void __launch_bounds__(256) k_gat2(
    const int* __restrict__ offs, const int* __restrict__ cnt, const int* __restrict__ csr,
    const float* __restrict__ s2s, const float* __restrict__ s2d,
    const float* __restrict__ h1c, float* __restrict__ agg)
{
    int d = blockIdx.x * 8 + (threadIdx.x >> 5);
    int lane = threadIdx.x & 31;
    if (d >= N_) return;
    int h8 = lane & 7;
    for (int t = 0; t < 2; t++) {
        const int* cs = csr + (size_t)t * E_;
        const float* ss = s2s + (size_t)t * N_ * 8;
        const float* sdp = s2d + (size_t)t * N_ * 8;
        int beg = offs[t * N_ + d], n = cnt[t * N_ + d];
        float sdv = __ldg(sdp + d * 8 + h8);
        float zp = 0.f;
        for (int e = 0; e < n; e += 4) {
            int idx = e + (lane >> 3);
            float val = 0.f;
            if (idx < n) {
                int s = cs[beg + idx];
                val = __expf(lrelu(__ldg(ss + s * 8 + h8) + sdv));
            }
            zp += val;
        }
        zp += __shfl_xor_sync(0xffffffffu, zp, 8);
        zp += __shfl_xor_sync(0xffffffffu, zp, 16);
        float inv = 1.f / zp;
        float4 acc[8];
#pragma unroll
        for (int h = 0; h < 8; h++) acc[h] = make_float4(0.f, 0.f, 0.f, 0.f);
        for (int e = 0; e < n; e += 4) {
            int idx = e + (lane >> 3);
            float val = 0.f; int smy = 0;
            if (idx < n) {
                smy = cs[beg + idx];
                val = __expf(lrelu(__ldg(ss + smy * 8 + h8) + sdv)) * inv;
            }
            int lim = n - e;
#pragma unroll
            for (int j = 0; j < 4; j++) {
                int sj = __shfl_sync(0xffffffffu, smy, j * 8);
                if (j < lim) {
                    float4 v = *(const float4*)(h1c + (size_t)sj * 128 + lane * 4);
#pragma unroll
                    for (int h = 0; h < 8; h++) {
                        float a = __shfl_sync(0xffffffffu, val, j * 8 + h);
                        acc[h].x = fmaf(a, v.x, acc[h].x);
                        acc[h].y = fmaf(a, v.y, acc[h].y);
                        acc[h].z = fmaf(a, v.z, acc[h].z);
                        acc[h].w = fmaf(a, v.w, acc[h].w);
                    }
                }
            }
        }
        float* ob = agg + (size_t)d * 2048 + t * 1024;
#pragma unroll
        for (int h = 0; h < 8; h++)
            *(float4*)(ob + h * 128 + lane * 4) = acc[h];
    }
}

// ---------------- deferred layer-2 GEMM: [N x 2048] @ [2048 x 64] ----------------
__global__ void __launch_bounds__(256) k_gemm3(
    const float* __restrict__ A, const float* __restrict__ B, float* __restrict__ C)
{
    __shared__ float As[16][128];
    __shared__ float Bs[16][64];
    int tid = threadIdx.x;
    int rg = (tid >> 4) << 2;
    int cg = (tid & 15) << 2;
    int rowBase = blockIdx.x * 128;
    float acc[8][4];
#pragma unroll
    for (int i = 0; i < 8; i++)
#pragma unroll
        for (int j = 0; j < 4; j++) acc[i][j] = 0.f;

    for (int k0 = 0; k0 < 2048; k0 += 16) {
#pragma unroll
        for (int i = 0; i < 2; i++) {
            int idx = tid + (i << 8);
            int r = idx >> 2;
            int c = (idx & 3) << 2;
            float4 v = make_float4(0.f, 0.f, 0.f, 0.f);
            int gr = rowBase + r;
            if (gr < N_) v = *(const float4*)(A + (size_t)gr * 2048 + k0 + c);
            As[c + 0][r] = v.x; As[c + 1][r] = v.y;
            As[c + 2][r] = v.z; As[c + 3][r] = v.w;
        }
        {
            int r = tid >> 4;
            int c = (tid & 15) << 2;
            float4 v = *(const float4*)(B + (size_t)(k0 + r) * 64 + c);
            *(float4*)&Bs[r][c] = v;
        }
        __syncthreads();
#pragma unroll
        for (int kk = 0; kk < 16; kk++) {
            float a[8], b[4];
            *(float4*)&a[0] = *(const float4*)&As[kk][rg];
            *(float4*)&a[4] = *(const float4*)&As[kk][rg + 64];
            *(float4*)&b[0] = *(const float4*)&Bs[kk][cg];
#pragma unroll
            for (int i = 0; i < 8; i++)
#pragma unroll
                for (int j = 0; j < 4; j++)
                    acc[i][j] = fmaf(a[i], b[j], acc[i][j]);
        }
        __syncthreads();
    }
#pragma unroll
    for (int i = 0; i < 8; i++) {
        int gr = rowBase + rg + (i < 4 ? i : 64 + i - 4);
        if (gr < N_)
            *(float4*)(C + (size_t)gr * 64 + cg) =
                make_float4(acc[i][0], acc[i][1], acc[i][2], acc[i][3]);
    }
}

// ---------------- classifier (bias + ELU fused): warp per node ----------------
__global__ void k_classifier(const float* __restrict__ h, const float* __restrict__ bc,
                             const float* __restrict__ Wc1, const float* __restrict__ bc1,
                             const float* __restrict__ Wc2, const float* __restrict__ bc2,
                             float* __restrict__ out)
{
    int wid = (blockIdx.x * blockDim.x + threadIdx.x) >> 5;
    int lane = threadIdx.x & 31;
    if (wid >= N_) return;
    const float* hr = h + (size_t)wid * 64;
    float acc = bc1[lane];
#pragma unroll
    for (int c = 0; c < 64; c++) {
        float hv = eluf(__ldg(hr + c) + __ldg(bc + c));
        acc = fmaf(hv, Wc1[c * 32 + lane], acc);
    }
    acc = fmaxf(acc, 0.f);
    float p0 = acc * Wc2[lane * 2];
    float p1 = acc * Wc2[lane * 2 + 1];
#pragma unroll
    for (int o = 16; o >= 1; o >>= 1) {
        p0 += __shfl_xor_sync(0xffffffffu, p0, o);
        p1 += __shfl_xor_sync(0xffffffffu, p1, o);
    }
    if (lane == 0) {
        out[wid * 2 + 0] = p0 + bc2[0];
        out[wid * 2 + 1] = p1 + bc2[1];
    }
}

// ---------------- launch ----------------
extern "C" void kernel_launch(void* const* d_in, const int* in_sizes, int n_in,
                              void* d_out, int out_size)
{
    const float* x    = (const float*)d_in[0];
    const void*  eia  = d_in[1];
    const void*  eib  = d_in[2];
    const float* W1   = (const float*)d_in[3];
    const float* a1s  = (const float*)d_in[4];
    const float* a1d  = (const float*)d_in[5];
    const float* b1   = (const float*)d_in[6];
    const float* W2   = (const float*)d_in[7];
    const float* a2s  = (const float*)d_in[8];
    const float* a2d  = (const float*)d_in[9];
    const float* b2   = (const float*)d_in[10];
    const float* Wc1  = (const float*)d_in[11];
    const float* bc1  = (const float*)d_in[12];
    const float* Wc2  = (const float*)d_in[13];
    const float* bc2  = (const float*)d_in[14];
    float* out = (float*)d_out;

    void* basev = nullptr;
    cudaGetSymbolAddress(&basev, g_scratch);
    unsigned char* base = (unsigned char*)basev;

    int*   p_src = (int*)(base + O_SRC);
    int*   p_dst = (int*)(base + O_DST);
    int*   p_csr = (int*)(base + O_CSR);
    int*   p_cnt = (int*)(base + O_CNT);
    int*   p_off = (int*)(base + O_OFF);
    int*   p_cur = (int*)(base + O_CUR);
    float* p_h1  = (float*)(base + O_H1);
    float* p_s1s = (float*)(base + O_S1S);
    float* p_s1d = (float*)(base + O_S1D);
    float* p_h1c = (float*)(base + O_H1C);
    float* p_s2s = (float*)(base + O_S2S);
    float* p_s2d = (float*)(base + O_S2D);
    float* p_ws  = (float*)(base + O_WS);
    float* p_wd  = (float*)(base + O_WD);
    float* p_w2c = (float*)(base + O_W2C);
    float* p_bc  = (float*)(base + O_BC);
    float* p_agg = (float*)(base + O_AGG);
    float* p_h2p = (float*)(base + O_H2P);

    // index handling + CSR build
    k_detect<<<1, 32>>>((const unsigned int*)eia);
    k_zeroi<<<(2 * N_ + 255) / 256, 256>>>(p_cnt, 2 * N_);
    k_cvt<<<dim3((E_ + 255) / 256, 2), 256>>>(eia, eib, p_src, p_dst, p_cnt);
    k_scan<<<2, 1024>>>(p_cnt, p_off, p_cur);
    k_scatter<<<(2 * E_ + 255) / 256, 256>>>(p_src, p_dst, p_cur, p_csr);
    k_prep<<<(135232 + 255) / 256, 256>>>(W2, a2s, a2d, b2, p_w2c, p_ws, p_wd, p_bc);

    // layer 1
    k_sgemm<256><<<dim3(157, 1, 2), 256>>>(x, W1, p_h1, N_, 128);
    k_scores<16><<<dim3((N_ + 7) / 8, 2), 256>>>(p_h1, a1s, a1d, p_s1s, p_s1d);
    k_gat1<<<(N_ + 7) / 8, 256>>>(p_off, p_cnt, p_csr, p_s1s, p_s1d, p_h1, b1, p_h1c);

    // layer 2 (aggregation in h1c domain, GEMM deferred)
    k_scores2<<<(N_ + 7) / 8, 256>>>(p_h1c, p_ws, p_wd, p_s2s, p_s2d);
    k_gat2<<<(N_ + 7) / 8, 256>>>(p_off, p_cnt, p_csr, p_s2s, p_s2d, p_h1c, p_agg);
    k_gemm3<<<157, 256>>>(p_agg, p_w2c, p_h2p);

    // classifier
    k_classifier<<<(N_ * 32 + 255) / 256, 256>>>(p_h2p, p_bc, Wc1, bc1, Wc2, bc2, out);
}